// round 17
// baseline (speedup 1.0000x reference)
#include <cuda_runtime.h>
#include <cstdint>

// RandomRoll: out[b,c,h,w] = x[b,c,(h - sh) & 511, (w - sw) & 511]
// x: [64, 3, 512, 512] fp32; shifts: [64, 2] int32.
// R17: one warp per 4-row quad (h = 4m..4m+3). Quad shares (b,c) -> same
// (sh,sw) -> same off/v0; the 4 source rows are consecutive (mod 512), so a
// warp reads one 8KB contiguous burst and writes one 8KB contiguous burst.
// 2-deep software pipeline (load row r+1 while realigning/storing row r)
// keeps regs ~44 and overlaps load latency with the shuffle/store phase.

static constexpr int HMASK = 511;
static constexpr int WMASK = 511;
static constexpr int TPB   = 256;
static constexpr unsigned FULL = 0xffffffffu;

// Realign output vec (lane + 32K) from in-register source row A[0..3].
// off warp-uniform (0..3). Neighbor of A[K]@lane is A[K]@lane+1; lane 31's
// neighbor is A[(K+1)&3]@lane0, contributed by lane 0 into the shuffle.
template<int K>
__device__ __forceinline__ float4 realign(const float4 A[4], int off, int lane)
{
    float4 a = A[K];
    if (off == 0) return a;
    const float4 an = A[(K + 1) & 3];
    int src = (lane + 1) & 31;
    float4 B;
    B.x = __shfl_sync(FULL, (lane == 0) ? an.x : a.x, src);
    B.y = __shfl_sync(FULL, (lane == 0) ? an.y : a.y, src);
    B.z = __shfl_sync(FULL, (lane == 0) ? an.z : a.z, src);
    B.w = __shfl_sync(FULL, (lane == 0) ? an.w : a.w, src);
    if (off == 1) return make_float4(a.y, a.z, a.w, B.x);
    if (off == 2) return make_float4(a.z, a.w, B.x, B.y);
    return make_float4(a.w, B.x, B.y, B.z);
}

__device__ __forceinline__ void load_row(float4 A[4], const float4* src, int v0, int lane)
{
    #pragma unroll
    for (int k = 0; k < 4; k++) A[k] = src[(v0 + lane + 32 * k) & 127];
}

__device__ __forceinline__ void store_row(float4* o, const float4 A[4], int off, int lane)
{
    o[ 0] = realign<0>(A, off, lane);
    o[32] = realign<1>(A, off, lane);
    o[64] = realign<2>(A, off, lane);
    o[96] = realign<3>(A, off, lane);
}

__global__ void __launch_bounds__(TPB)
random_roll_quads(const float4* __restrict__ x4,
                  const int*    __restrict__ shifts,
                  float4*       __restrict__ out4,
                  int n_quads)   // groups of 4 rows; row = (b*3+c)*512 + h
{
    int lane = threadIdx.x & 31;
    int quad = blockIdx.x * (TPB / 32) + (threadIdx.x >> 5);
    if (quad >= n_quads) return;

    int row0 = quad << 2;            // h multiple of 4; rows row0..row0+3 share bc
    int h0   = row0 & HMASK;
    int bc   = row0 >> 9;
    int b    = bc / 3;

    int sh = __ldg(&shifts[2 * b]);
    int sw = __ldg(&shifts[2 * b + 1]);

    int src_h0 = (h0 - sh) & HMASK;
    const float4* plane = x4 + ((size_t)bc << 16);   // 512 rows * 128 vec4
    int s0  = (-sw) & WMASK;         // first source float of each rolled row
    int off = s0 & 3;                // shared by all 4 rows (same sw)
    int v0  = s0 >> 2;

    float4* o = out4 + ((size_t)row0 << 7) + lane;

    // 2-deep pipeline over the 4 rows: load r+1 while realigning/storing r.
    float4 Acur[4], Anxt[4];
    load_row(Acur, plane + ((size_t)src_h0 << 7), v0, lane);

    #pragma unroll
    for (int r = 0; r < 4; r++) {
        if (r < 3) {
            int src_h = (src_h0 + r + 1) & HMASK;
            load_row(Anxt, plane + ((size_t)src_h << 7), v0, lane);
        }
        store_row(o + (r << 7), Acur, off, lane);
        #pragma unroll
        for (int k = 0; k < 4; k++) Acur[k] = Anxt[k];
    }
}

// Scalar tail (defensive; these shapes divide into whole quads).
__global__ void random_roll_tail(const float* __restrict__ x,
                                 const int*   __restrict__ shifts,
                                 float*       __restrict__ out,
                                 int start, int total)
{
    int i = start + blockIdx.x * blockDim.x + threadIdx.x;
    if (i >= total) return;
    int w   = i & WMASK;
    int row = i >> 9;
    int h   = row & HMASK;
    int bc  = row >> 9;
    int b   = bc / 3;
    int sh = shifts[2 * b];
    int sw = shifts[2 * b + 1];
    out[i] = x[(((size_t)((bc << 9) | ((h - sh) & HMASK))) << 9) + ((w - sw) & WMASK)];
}

extern "C" void kernel_launch(void* const* d_in, const int* in_sizes, int n_in,
                              void* d_out, int out_size)
{
    const float4* x4     = (const float4*)d_in[0];
    const int*    shifts = (const int*)d_in[1];
    float4*       out4   = (float4*)d_out;

    int n_rows  = out_size >> 9;                 // whole 512-float rows
    int n_quads = n_rows >> 2;                   // H=512 -> rows group in 4s
    if (n_quads > 0) {
        int wpb    = TPB / 32;                   // 8 quads per block
        int blocks = (n_quads + wpb - 1) / wpb;
        random_roll_quads<<<blocks, TPB>>>(x4, shifts, out4, n_quads);
    }
    int tail_start = (n_quads << 2) << 9;
    int tail = out_size - tail_start;
    if (tail > 0) {
        random_roll_tail<<<(tail + 255) / 256, 256>>>((const float*)d_in[0], shifts,
                                                      (float*)d_out, tail_start, out_size);
    }
}